// round 4
// baseline (speedup 1.0000x reference)
#include <cuda_runtime.h>
#include <cuda_bf16.h>
#include <math.h>

#define HDIM 256
#define BSEG 4096
#define K1   (3 * HDIM)   // 768

// Scratch (device globals — allocation is forbidden)
__device__ float g_psum[2 * BSEG * HDIM];   // [8192, 256] half-segment partial sums
__device__ float g_pmax[2 * BSEG * HDIM];   // [8192, 256] half-segment partial maxes
__device__ float g_combined[BSEG * K1];     // [B, 3H] = mean | sum | max
__device__ float g_hidden[BSEG * HDIM];     // [B, H]

__device__ __forceinline__ int lower_bound_i32(const int* __restrict__ a,
                                               int n, int v) {
    int lo = 0, hi = n;
    while (lo < hi) {
        int mid = (lo + hi) >> 1;
        if (a[mid] < v) lo = mid + 1; else hi = mid;
    }
    return lo;
}

__device__ __forceinline__ void acc4(float4& s, float4& m, const float4 v) {
    s.x += v.x; s.y += v.y; s.z += v.z; s.w += v.w;
    m.x = fmaxf(m.x, v.x); m.y = fmaxf(m.y, v.y);
    m.z = fmaxf(m.z, v.z); m.w = fmaxf(m.w, v.w);
}

// ---------------------------------------------------------------------------
// Stage 1a: half-segment partial pooling. Block blk = 2*b + h reduces half h
// of segment b. 256 threads = 4 row-groups x 64 lanes; 4 rows in flight.
// ---------------------------------------------------------------------------
__global__ void __launch_bounds__(256)
pool_partial(const float4* __restrict__ feat4,   // [N, 64] float4
             const int* __restrict__ batch,
             float4* __restrict__ psum4,          // [8192, 64] float4
             float4* __restrict__ pmax4,
             int n_rows) {
    const int blk = blockIdx.x;
    const int b = blk >> 1;
    const int h = blk & 1;
    const int t = threadIdx.x;
    const int g = t >> 6;   // 0..3
    const int c = t & 63;   // 0..63

    __shared__ int s_se[2];
    if (t < 2) s_se[t] = lower_bound_i32(batch, n_rows, b + t);
    __syncthreads();
    const int start = s_se[0];
    const int end   = s_se[1];
    const int mid   = start + ((end - start + 1) >> 1);
    const int r0    = h ? mid : start;
    const int r1    = h ? end : mid;

    float4 s0 = make_float4(0.f, 0.f, 0.f, 0.f), s1 = s0, s2 = s0, s3 = s0;
    float4 m0 = make_float4(-INFINITY, -INFINITY, -INFINITY, -INFINITY);
    float4 m1 = m0, m2 = m0, m3 = m0;

    int i = r0 + g;
    for (; i + 12 < r1; i += 16) {
        float4 v0 = feat4[(size_t)(i +  0) * 64 + c];
        float4 v1 = feat4[(size_t)(i +  4) * 64 + c];
        float4 v2 = feat4[(size_t)(i +  8) * 64 + c];
        float4 v3 = feat4[(size_t)(i + 12) * 64 + c];
        acc4(s0, m0, v0); acc4(s1, m1, v1);
        acc4(s2, m2, v2); acc4(s3, m3, v3);
    }
    for (; i < r1; i += 4) {
        float4 v = feat4[(size_t)i * 64 + c];
        acc4(s0, m0, v);
    }
    float4 s = make_float4((s0.x + s1.x) + (s2.x + s3.x),
                           (s0.y + s1.y) + (s2.y + s3.y),
                           (s0.z + s1.z) + (s2.z + s3.z),
                           (s0.w + s1.w) + (s2.w + s3.w));
    float4 m = make_float4(fmaxf(fmaxf(m0.x, m1.x), fmaxf(m2.x, m3.x)),
                           fmaxf(fmaxf(m0.y, m1.y), fmaxf(m2.y, m3.y)),
                           fmaxf(fmaxf(m0.z, m1.z), fmaxf(m2.z, m3.z)),
                           fmaxf(fmaxf(m0.w, m1.w), fmaxf(m2.w, m3.w)));

    __shared__ float4 red_s[4][64];
    __shared__ float4 red_m[4][64];
    red_s[g][c] = s;
    red_m[g][c] = m;
    __syncthreads();

    if (t < 64) {
        float4 S = red_s[0][t], M = red_m[0][t];
        #pragma unroll
        for (int gg = 1; gg < 4; ++gg) {
            float4 ps = red_s[gg][t], pm = red_m[gg][t];
            S.x += ps.x; S.y += ps.y; S.z += ps.z; S.w += ps.w;
            M.x = fmaxf(M.x, pm.x); M.y = fmaxf(M.y, pm.y);
            M.z = fmaxf(M.z, pm.z); M.w = fmaxf(M.w, pm.w);
        }
        psum4[(size_t)blk * 64 + t] = S;
        pmax4[(size_t)blk * 64 + t] = M;
    }
}

// ---------------------------------------------------------------------------
// Stage 1b: combine half-segment partials -> combined [B, 3H].
// 1024 blocks x 256 threads; each block handles 4 segments.
// ---------------------------------------------------------------------------
__global__ void __launch_bounds__(256)
pool_finalize(const int* __restrict__ batch,
              const float4* __restrict__ psum4,
              const float4* __restrict__ pmax4,
              float4* __restrict__ combined4,     // [B, 192] float4
              int n_rows) {
    const int t = threadIdx.x;
    const int seg = blockIdx.x * 4 + (t >> 6);
    const int c = t & 63;

    __shared__ int bounds[5];
    if (t < 5) bounds[t] = lower_bound_i32(batch, n_rows, blockIdx.x * 4 + t);
    __syncthreads();
    const int cnt = bounds[(t >> 6) + 1] - bounds[t >> 6];

    float4 Sa = psum4[(size_t)(2 * seg) * 64 + c];
    float4 Sb = psum4[(size_t)(2 * seg + 1) * 64 + c];
    float4 Ma = pmax4[(size_t)(2 * seg) * 64 + c];
    float4 Mb = pmax4[(size_t)(2 * seg + 1) * 64 + c];

    float4 S = make_float4(Sa.x + Sb.x, Sa.y + Sb.y, Sa.z + Sb.z, Sa.w + Sb.w);
    float4 M = make_float4(fmaxf(Ma.x, Mb.x), fmaxf(Ma.y, Mb.y),
                           fmaxf(Ma.z, Mb.z), fmaxf(Ma.w, Mb.w));
    float inv = (cnt > 0) ? (1.0f / (float)cnt) : 0.0f;
    if (cnt == 0) { S = make_float4(0.f, 0.f, 0.f, 0.f); M = S; }
    float4 mean = make_float4(S.x * inv, S.y * inv, S.z * inv, S.w * inv);

    float4* row = combined4 + (size_t)seg * 192;
    row[c]       = mean;
    row[64 + c]  = S;
    row[128 + c] = M;
}

// ---------------------------------------------------------------------------
// Stage 2/3: double-buffered SMEM-tiled GEMM using packed fma.rn.f32x2.
// C[M,N] = act(A[M,K] @ W[K,N] + bias). BM=BN=64, BK=32, 256 threads, 4x4.
// ---------------------------------------------------------------------------
__device__ __forceinline__ unsigned long long pack2(float x) {
    unsigned long long r;
    asm("mov.b64 %0, {%1, %1};" : "=l"(r) : "f"(x));
    return r;
}
#define FFMA2(acc, a, b) \
    asm("fma.rn.f32x2 %0, %1, %2, %0;" : "+l"(acc) : "l"(a), "l"(b))

__global__ void __launch_bounds__(256)
gemm_bias_act(const float* __restrict__ A,
              const float* __restrict__ W,
              const float* __restrict__ bias,
              float* __restrict__ C,
              int M, int K, int N, int do_silu) {
    __shared__ float As[2][32][68];  // [buf][k][m], stride 68 keeps 16B alignment
    __shared__ float Bs[2][32][64];  // [buf][k][n]

    const int tid = threadIdx.x;
    const int tx  = tid & 15;
    const int ty  = tid >> 4;
    const int bm  = blockIdx.y * 64;
    const int bn  = blockIdx.x * 64;

    const int la0_r = tid >> 3,          la0_c = (tid & 7) * 4;
    const int la1_r = (tid + 256) >> 3,  la1_c = ((tid + 256) & 7) * 4;
    const int lb0_r = tid >> 4,          lb0_n = (tid & 15) * 4;
    const int lb1_r = (tid + 256) >> 4,  lb1_n = ((tid + 256) & 15) * 4;

    const int nk = K >> 5;
    float4 a0, a1, w0, w1;

    a0 = *(const float4*)&A[(size_t)(bm + la0_r) * K + la0_c];
    a1 = *(const float4*)&A[(size_t)(bm + la1_r) * K + la1_c];
    w0 = *(const float4*)&W[(size_t)lb0_r * N + bn + lb0_n];
    w1 = *(const float4*)&W[(size_t)lb1_r * N + bn + lb1_n];

    As[0][la0_c + 0][la0_r] = a0.x; As[0][la0_c + 1][la0_r] = a0.y;
    As[0][la0_c + 2][la0_r] = a0.z; As[0][la0_c + 3][la0_r] = a0.w;
    As[0][la1_c + 0][la1_r] = a1.x; As[0][la1_c + 1][la1_r] = a1.y;
    As[0][la1_c + 2][la1_r] = a1.z; As[0][la1_c + 3][la1_r] = a1.w;
    *(float4*)&Bs[0][lb0_r][lb0_n] = w0;
    *(float4*)&Bs[0][lb1_r][lb1_n] = w1;
    __syncthreads();

    unsigned long long acc2[4][2] = {};   // {0.f,0.f} packed == 0ull

    for (int kk = 0; kk < nk; ++kk) {
        const int buf = kk & 1;
        if (kk + 1 < nk) {
            const int k0 = (kk + 1) << 5;
            a0 = *(const float4*)&A[(size_t)(bm + la0_r) * K + k0 + la0_c];
            a1 = *(const float4*)&A[(size_t)(bm + la1_r) * K + k0 + la1_c];
            w0 = *(const float4*)&W[(size_t)(k0 + lb0_r) * N + bn + lb0_n];
            w1 = *(const float4*)&W[(size_t)(k0 + lb1_r) * N + bn + lb1_n];
        }

        #pragma unroll
        for (int k = 0; k < 32; ++k) {
            const float4 av = *(const float4*)&As[buf][k][ty * 4];
            const ulonglong2 bp = *(const ulonglong2*)&Bs[buf][k][tx * 4];
            const unsigned long long ap0 = pack2(av.x);
            const unsigned long long ap1 = pack2(av.y);
            const unsigned long long ap2 = pack2(av.z);
            const unsigned long long ap3 = pack2(av.w);
            FFMA2(acc2[0][0], ap0, bp.x); FFMA2(acc2[0][1], ap0, bp.y);
            FFMA2(acc2[1][0], ap1, bp.x); FFMA2(acc2[1][1], ap1, bp.y);
            FFMA2(acc2[2][0], ap2, bp.x); FFMA2(acc2[2][1], ap2, bp.y);
            FFMA2(acc2[3][0], ap3, bp.x); FFMA2(acc2[3][1], ap3, bp.y);
        }

        if (kk + 1 < nk) {
            const int nb = buf ^ 1;
            As[nb][la0_c + 0][la0_r] = a0.x; As[nb][la0_c + 1][la0_r] = a0.y;
            As[nb][la0_c + 2][la0_r] = a0.z; As[nb][la0_c + 3][la0_r] = a0.w;
            As[nb][la1_c + 0][la1_r] = a1.x; As[nb][la1_c + 1][la1_r] = a1.y;
            As[nb][la1_c + 2][la1_r] = a1.z; As[nb][la1_c + 3][la1_r] = a1.w;
            *(float4*)&Bs[nb][lb0_r][lb0_n] = w0;
            *(float4*)&Bs[nb][lb1_r][lb1_n] = w1;
            __syncthreads();
        }
    }

    const float4 bv4 = *(const float4*)&bias[bn + tx * 4];
    #pragma unroll
    for (int iu = 0; iu < 4; ++iu) {
        const int m = bm + ty * 4 + iu;
        float x0, x1, x2, x3;
        asm("mov.b64 {%0, %1}, %2;" : "=f"(x0), "=f"(x1) : "l"(acc2[iu][0]));
        asm("mov.b64 {%0, %1}, %2;" : "=f"(x2), "=f"(x3) : "l"(acc2[iu][1]));
        x0 += bv4.x; x1 += bv4.y; x2 += bv4.z; x3 += bv4.w;
        if (do_silu) {
            x0 = x0 / (1.0f + __expf(-x0));
            x1 = x1 / (1.0f + __expf(-x1));
            x2 = x2 / (1.0f + __expf(-x2));
            x3 = x3 / (1.0f + __expf(-x3));
        }
        *(float4*)&C[(size_t)m * N + bn + tx * 4] = make_float4(x0, x1, x2, x3);
    }
}

// ---------------------------------------------------------------------------
extern "C" void kernel_launch(void* const* d_in, const int* in_sizes, int n_in,
                              void* d_out, int out_size) {
    const float* feat  = (const float*)d_in[0];
    const int*   batch = (const int*)d_in[1];
    const float* W1    = (const float*)d_in[2];
    const float* b1    = (const float*)d_in[3];
    const float* W2    = (const float*)d_in[4];
    const float* b2    = (const float*)d_in[5];
    float*       out   = (float*)d_out;

    const int n_rows = in_sizes[1];

    float *psum, *pmax, *combined, *hidden;
    cudaGetSymbolAddress((void**)&psum,     g_psum);
    cudaGetSymbolAddress((void**)&pmax,     g_pmax);
    cudaGetSymbolAddress((void**)&combined, g_combined);
    cudaGetSymbolAddress((void**)&hidden,   g_hidden);

    pool_partial<<<2 * BSEG, 256>>>((const float4*)feat, batch,
                                    (float4*)psum, (float4*)pmax, n_rows);
    pool_finalize<<<BSEG / 4, 256>>>(batch, (const float4*)psum,
                                     (const float4*)pmax,
                                     (float4*)combined, n_rows);

    dim3 g1(HDIM / 64, BSEG / 64);
    gemm_bias_act<<<g1, 256>>>(combined, W1, b1, hidden, BSEG, K1, HDIM, 1);

    dim3 g2(HDIM / 64, BSEG / 64);
    gemm_bias_act<<<g2, 256>>>(hidden, W2, b2, out, BSEG, HDIM, HDIM, 0);
}